// round 6
// baseline (speedup 1.0000x reference)
#include <cuda_runtime.h>
#include <math_constants.h>

#define N_    256
#define D_    512
#define Q_    2048
#define C_    1000
#define IMG_  150528   // 3*224*224
#define IMG4_ 37632    // IMG_/4 = 21 * 1792
#define K_    4

// Output layout: labels | probs | images | grads (return order, float32)
#define OFF_LABELS 0
#define OFF_PROBS  (N_)
#define OFF_IMG    (N_ + N_*C_)
#define OFF_GRADS  (N_ + N_*C_ + N_*IMG_)

// Mega-kernel block roles (1-D grid)
#define NB_DIST 128            // 32 row-groups x 4 q-chunks
#define NB_TOPK 128            // 2 rows per block
#define NB_CONS (N_ * 22)      // 21 image chunks + 1 probs/grads per row
#define NB_ALL  (NB_DIST + NB_TOPK + NB_CONS)

// Scratch (no cudaMalloc allowed; reset/overwritten every call => deterministic)
__device__ float  g_dist[N_ * Q_];
__device__ int    g_topk[N_ * K_];
__device__ float4 g_bankT[128 * Q_];   // bankT[cf4][q] : 4 MB, L2-resident
__device__ int    g_grp_cnt[32];       // dist q-chunks completed per row-group
__device__ int    g_ready[N_];         // topk published for row n

// packed f32x2 FMA (ptxas only emits FFMA2 via explicit PTX)
__device__ __forceinline__ void ffma2(unsigned long long& acc,
                                      unsigned long long a,
                                      unsigned long long b) {
    asm("fma.rn.f32x2 %0, %1, %2, %0;" : "+l"(acc) : "l"(a), "l"(b));
}
__device__ __forceinline__ float unpack_sum(unsigned long long v) {
    float lo = __uint_as_float((unsigned)(v & 0xffffffffull));
    float hi = __uint_as_float((unsigned)(v >> 32));
    return lo + hi;
}

// ---------------------------------------------------------------------------
// Kernel 1: transpose bank to bankT[cf4][q] (coalesced dist loads) AND reset
// the flags for this invocation (stream order makes them visible to kernel 2).
// ---------------------------------------------------------------------------
__global__ void transpose_kernel(const float4* __restrict__ bank4) {
    if (blockIdx.x == 0 && blockIdx.y == 0) {
        if (threadIdx.x < N_)  g_ready[threadIdx.x] = 0;
        if (threadIdx.x < 32)  g_grp_cnt[threadIdx.x] = 0;
    }
    __shared__ float4 tile[32][33];
    const int tx = threadIdx.x & 31;
    const int ty = threadIdx.x >> 5;
    const int qt = blockIdx.x * 32;
    const int ct = blockIdx.y * 32;
    #pragma unroll
    for (int i = 0; i < 4; i++)
        tile[ty + 8 * i][tx] = bank4[(size_t)(qt + ty + 8 * i) * 128 + ct + tx];
    __syncthreads();
    #pragma unroll
    for (int i = 0; i < 4; i++)
        g_bankT[(size_t)(ct + ty + 8 * i) * Q_ + qt + tx] = tile[tx][ty + 8 * i];
}

// ---------------------------------------------------------------------------
// Kernel 2 (mega): dist producers + topk + gather consumers in one launch.
// All 256 producer blocks are guaranteed resident in wave 1 (>=2 blocks/SM),
// so consumer spin-waits cannot deadlock.
// ---------------------------------------------------------------------------
__global__ void __launch_bounds__(256) mega_kernel(const float4* __restrict__ feats4,
                                                   const float4* __restrict__ img4,
                                                   const float*  __restrict__ bank,
                                                   const float*  __restrict__ probs,
                                                   float* __restrict__ out) {
    __shared__ float s_mem[4096];      // 16 KB: dist feats tile / topk row buffer
    __shared__ float s_wv[8];
    __shared__ int   s_wi[8];
    const int bid = blockIdx.x;
    const int tid = threadIdx.x;
    const int lane = tid & 31, w = tid >> 5;

    if (bid < NB_DIST) {
        // ---------------- dist: 8 rows x 512 q, qpt=2 ----------------
        const int grp = bid >> 2;              // 0..31
        const int r0  = grp * 8;
        const int qb  = (bid & 3) * 512;

        float4* s_feat = reinterpret_cast<float4*>(s_mem);   // 8 x 128 float4
        #pragma unroll
        for (int i = tid; i < 8 * 128; i += 256)
            s_feat[i] = feats4[(size_t)r0 * 128 + i];
        __syncthreads();

        // feature norms: warp w reduces row w
        __shared__ float s_inv[8];
        {
            float ss = 0.0f;
            #pragma unroll
            for (int c = lane; c < 128; c += 32) {
                float4 v = s_feat[w * 128 + c];
                ss += v.x * v.x + v.y * v.y + v.z * v.z + v.w * v.w;
            }
            #pragma unroll
            for (int o = 16; o > 0; o >>= 1)
                ss += __shfl_xor_sync(0xffffffffu, ss, o);
            if (lane == 0) s_inv[w] = 1.0f / fmaxf(sqrtf(ss), 1e-12f);
        }
        __syncthreads();

        unsigned long long acc[8][2];
        unsigned long long bb[2] = {0ull, 0ull};
        #pragma unroll
        for (int r = 0; r < 8; r++) { acc[r][0] = 0ull; acc[r][1] = 0ull; }

        const ulonglong2* bT = reinterpret_cast<const ulonglong2*>(g_bankT) + qb + tid;
        const ulonglong2* sf = reinterpret_cast<const ulonglong2*>(s_feat);

        #pragma unroll 4
        for (int c = 0; c < 128; c++) {
            ulonglong2 b0 = bT[(size_t)c * Q_];
            ulonglong2 b1 = bT[(size_t)c * Q_ + 256];
            ffma2(bb[0], b0.x, b0.x); ffma2(bb[0], b0.y, b0.y);
            ffma2(bb[1], b1.x, b1.x); ffma2(bb[1], b1.y, b1.y);
            #pragma unroll
            for (int r = 0; r < 8; r++) {
                ulonglong2 f = sf[r * 128 + c];     // warp-broadcast
                ffma2(acc[r][0], f.x, b0.x); ffma2(acc[r][0], f.y, b0.y);
                ffma2(acc[r][1], f.x, b1.x); ffma2(acc[r][1], f.y, b1.y);
            }
        }

        #pragma unroll
        for (int j = 0; j < 2; j++) {
            const int q = qb + tid + 256 * j;
            const float ibn = 1.0f / fmaxf(sqrtf(unpack_sum(bb[j])), 1e-12f);
            #pragma unroll
            for (int r = 0; r < 8; r++) {
                float dot = unpack_sum(acc[r][j]);
                g_dist[(size_t)(r0 + r) * Q_ + q] = 1.0f - dot * s_inv[r] * ibn;
            }
        }

        __threadfence();       // release this thread's g_dist writes
        __syncthreads();       // all threads' fences done before the signal
        if (tid == 0) atomicAdd(&g_grp_cnt[grp], 1);

    } else if (bid < NB_DIST + NB_TOPK) {
        // ---------------- topk: rows 2m, 2m+1 ----------------
        const int m = bid - NB_DIST;
        const int grp = m >> 2;                     // rows 8*grp..8*grp+7
        if (tid == 0) {
            while (atomicAdd(&g_grp_cnt[grp], 0) < 4) __nanosleep(100);
        }
        __syncthreads();
        __threadfence();       // acquire: order g_dist reads after flag

        float* s_d = s_mem;    // 2048 floats (8 KB)
        for (int row = 2 * m; row < 2 * m + 2; row++) {
            for (int qq = tid; qq < Q_; qq += 256)
                s_d[qq] = g_dist[(size_t)row * Q_ + qq];
            __syncthreads();

            for (int k = 0; k < K_; k++) {
                float bv = -CUDART_INF_F; int bi = Q_;
                #pragma unroll
                for (int t = 0; t < 8; t++) {
                    int qq = tid + t * 256;             // ascending per thread
                    float v = s_d[qq];
                    if (v > bv) { bv = v; bi = qq; }    // strict > keeps lowest idx
                }
                #pragma unroll
                for (int o = 16; o > 0; o >>= 1) {
                    float ov = __shfl_xor_sync(0xffffffffu, bv, o);
                    int   oi = __shfl_xor_sync(0xffffffffu, bi, o);
                    if (ov > bv || (ov == bv && oi < bi)) { bv = ov; bi = oi; }
                }
                if (lane == 0) { s_wv[w] = bv; s_wi[w] = bi; }
                __syncthreads();
                if (tid == 0) {
                    float v2 = s_wv[0]; int i2 = s_wi[0];
                    #pragma unroll
                    for (int p = 1; p < 8; p++)
                        if (s_wv[p] > v2 || (s_wv[p] == v2 && s_wi[p] < i2)) {
                            v2 = s_wv[p]; i2 = s_wi[p];
                        }
                    g_topk[row * K_ + k] = i2;
                    s_d[i2] = -CUDART_INF_F;            // mask for next pass
                }
                __syncthreads();
            }
            if (tid == 0) {
                __threadfence();                        // release g_topk[row]
                atomicExch(&g_ready[row], 1);
            }
            __syncthreads();
        }

    } else {
        // ---------------- consumers: image chunks + probs/grads ----------------
        const int cid = bid - NB_DIST - NB_TOPK;
        const int n   = cid & 255;
        const int ch  = cid >> 8;                      // 0..21
        if (tid == 0) {
            while (atomicAdd(&g_ready[n], 0) == 0) __nanosleep(200);
        }
        __syncthreads();
        __threadfence();       // acquire: order g_topk reads after flag

        const int4 ii = *reinterpret_cast<const int4*>(&g_topk[n * K_]);
        const int i0 = ii.x, i1 = ii.y, i2 = ii.z, i3 = ii.w;

        if (ch < 21) {
            const int base = ch * 1792 + tid;
            const float4* p0 = img4 + (size_t)i0 * IMG4_;
            const float4* p1 = img4 + (size_t)i1 * IMG4_;
            const float4* p2 = img4 + (size_t)i2 * IMG4_;
            const float4* p3 = img4 + (size_t)i3 * IMG4_;
            float4* po = reinterpret_cast<float4*>(out + OFF_IMG) + (size_t)n * IMG4_;
            #pragma unroll
            for (int t = 0; t < 7; t++) {
                const int j = base + t * 256;
                float4 a = p0[j];
                float4 b = p1[j];
                float4 c = p2[j];
                float4 d = p3[j];
                float4 r;
                r.x = 0.25f * (a.x + b.x + c.x + d.x);
                r.y = 0.25f * (a.y + b.y + c.y + d.y);
                r.z = 0.25f * (a.z + b.z + c.z + d.z);
                r.w = 0.25f * (a.w + b.w + c.w + d.w);
                __stcs(po + j, r);
            }
        } else {
            // grads mean (512)
            float* outg = out + OFF_GRADS + (size_t)n * D_;
            for (int d = tid; d < D_; d += 256)
                outg[d] = 0.25f * (bank[(size_t)i0 * D_ + d] + bank[(size_t)i1 * D_ + d] +
                                   bank[(size_t)i2 * D_ + d] + bank[(size_t)i3 * D_ + d]);
            // probs mean (1000) + argmax -> label
            float* outp = out + OFF_PROBS + (size_t)n * C_;
            float bv = -CUDART_INF_F; int bc = C_;
            for (int c = tid; c < C_; c += 256) {
                float p = 0.25f * (probs[(size_t)i0 * C_ + c] + probs[(size_t)i1 * C_ + c] +
                                   probs[(size_t)i2 * C_ + c] + probs[(size_t)i3 * C_ + c]);
                outp[c] = p;
                if (p > bv) { bv = p; bc = c; }          // ascending c per thread
            }
            #pragma unroll
            for (int o = 16; o > 0; o >>= 1) {
                float ov = __shfl_xor_sync(0xffffffffu, bv, o);
                int   oi = __shfl_xor_sync(0xffffffffu, bc, o);
                if (ov > bv || (ov == bv && oi < bc)) { bv = ov; bc = oi; }
            }
            if (lane == 0) { s_wv[w] = bv; s_wi[w] = bc; }
            __syncthreads();
            if (tid == 0) {
                float v2 = s_wv[0]; int ib = s_wi[0];
                #pragma unroll
                for (int p = 1; p < 8; p++)
                    if (s_wv[p] > v2 || (s_wv[p] == v2 && s_wi[p] < ib)) {
                        v2 = s_wv[p]; ib = s_wi[p];
                    }
                out[OFF_LABELS + n] = (float)ib;
            }
        }
    }
}

// ---------------------------------------------------------------------------
extern "C" void kernel_launch(void* const* d_in, const int* in_sizes, int n_in,
                              void* d_out, int out_size) {
    const float* feats = (const float*)d_in[0];   // (256, 512)
    const float* bank  = (const float*)d_in[1];   // (2048, 512)
    const float* probs = (const float*)d_in[2];   // (2048, 1000)
    const float* img   = (const float*)d_in[3];   // (2048, 3, 224, 224)
    float* out = (float*)d_out;

    transpose_kernel<<<dim3(Q_ / 32, 128 / 32), 256>>>(
        reinterpret_cast<const float4*>(bank));
    mega_kernel<<<NB_ALL, 256>>>(
        reinterpret_cast<const float4*>(feats),
        reinterpret_cast<const float4*>(img),
        bank, probs, out);
}

// round 7
// speedup vs baseline: 1.0405x; 1.0405x over previous
#include <cuda_runtime.h>
#include <math_constants.h>

#define N_    256
#define D_    512
#define Q_    2048
#define C_    1000
#define IMG_  150528   // 3*224*224
#define IMG4_ 37632    // IMG_/4 = 21 * 1792
#define K_    4

// Output layout: labels | probs | images | grads (return order, float32)
#define OFF_LABELS 0
#define OFF_PROBS  (N_)
#define OFF_IMG    (N_ + N_*C_)
#define OFF_GRADS  (N_ + N_*C_ + N_*IMG_)

// Scratch (no cudaMalloc allowed; overwritten every call => deterministic)
__device__ int    g_topk[N_ * K_];
__device__ float4 g_bankT[128 * Q_];     // bankT[cf4][q] : 4 MB, L2-resident
__device__ float  g_cv[N_ * 16];         // per-(row,chunk) top-4 candidate values
__device__ int    g_ci[N_ * 16];         // ... and their global q indices

// packed f32x2 FMA (ptxas only emits FFMA2 via explicit PTX)
__device__ __forceinline__ void ffma2(unsigned long long& acc,
                                      unsigned long long a,
                                      unsigned long long b) {
    asm("fma.rn.f32x2 %0, %1, %2, %0;" : "+l"(acc) : "l"(a), "l"(b));
}
__device__ __forceinline__ float unpack_sum(unsigned long long v) {
    float lo = __uint_as_float((unsigned)(v & 0xffffffffull));
    float hi = __uint_as_float((unsigned)(v >> 32));
    return lo + hi;
}

// ---------------------------------------------------------------------------
// Kernel 1: transpose bank to bankT[cf4][q] so dist's bank loads are
// warp-coalesced (consecutive q per lane).
// ---------------------------------------------------------------------------
__global__ void transpose_kernel(const float4* __restrict__ bank4) {
    __shared__ float4 tile[32][33];
    const int tx = threadIdx.x & 31;
    const int ty = threadIdx.x >> 5;
    const int qt = blockIdx.x * 32;
    const int ct = blockIdx.y * 32;
    #pragma unroll
    for (int i = 0; i < 4; i++)
        tile[ty + 8 * i][tx] = bank4[(size_t)(qt + ty + 8 * i) * 128 + ct + tx];
    __syncthreads();
    #pragma unroll
    for (int i = 0; i < 4; i++)
        g_bankT[(size_t)(ct + ty + 8 * i) * Q_ + qt + tx] = tile[tx][ty + 8 * i];
}

// ---------------------------------------------------------------------------
// Kernel 2: dist + per-chunk top-4. Grid (4 q-chunks x 32 row-groups),
// 256 threads. Thread tile: 8 rows x 2 q. After the dot-product mainloop the
// 8x512 distance tile is transposed into smem and each warp extracts the
// top-4 (value desc, index asc) of its row within this chunk.
// No global distance matrix is ever written.
// ---------------------------------------------------------------------------
__global__ void __launch_bounds__(256) dist_kernel(const float4* __restrict__ feats4) {
    __shared__ float s_mem[8 * 512];     // feats tile (float4 view) -> d tile
    __shared__ float s_inv[8];
    const int tid = threadIdx.x;
    const int lane = tid & 31, w = tid >> 5;
    const int grp = blockIdx.y;            // 0..31
    const int r0  = grp * 8;
    const int qb  = blockIdx.x * 512;

    float4* s_feat = reinterpret_cast<float4*>(s_mem);   // 8 x 128 float4
    #pragma unroll
    for (int i = tid; i < 8 * 128; i += 256)
        s_feat[i] = feats4[(size_t)r0 * 128 + i];
    __syncthreads();

    // feature norms: warp w reduces row w
    {
        float ss = 0.0f;
        #pragma unroll
        for (int c = lane; c < 128; c += 32) {
            float4 v = s_feat[w * 128 + c];
            ss += v.x * v.x + v.y * v.y + v.z * v.z + v.w * v.w;
        }
        #pragma unroll
        for (int o = 16; o > 0; o >>= 1)
            ss += __shfl_xor_sync(0xffffffffu, ss, o);
        if (lane == 0) s_inv[w] = 1.0f / fmaxf(sqrtf(ss), 1e-12f);
    }
    __syncthreads();

    unsigned long long acc[8][2];
    unsigned long long bb[2] = {0ull, 0ull};
    #pragma unroll
    for (int r = 0; r < 8; r++) { acc[r][0] = 0ull; acc[r][1] = 0ull; }

    const ulonglong2* bT = reinterpret_cast<const ulonglong2*>(g_bankT) + qb + tid;
    const ulonglong2* sf = reinterpret_cast<const ulonglong2*>(s_mem);

    #pragma unroll 4
    for (int c = 0; c < 128; c++) {
        ulonglong2 b0 = bT[(size_t)c * Q_];
        ulonglong2 b1 = bT[(size_t)c * Q_ + 256];
        ffma2(bb[0], b0.x, b0.x); ffma2(bb[0], b0.y, b0.y);
        ffma2(bb[1], b1.x, b1.x); ffma2(bb[1], b1.y, b1.y);
        #pragma unroll
        for (int r = 0; r < 8; r++) {
            ulonglong2 f = sf[r * 128 + c];     // warp-broadcast
            ffma2(acc[r][0], f.x, b0.x); ffma2(acc[r][0], f.y, b0.y);
            ffma2(acc[r][1], f.x, b1.x); ffma2(acc[r][1], f.y, b1.y);
        }
    }

    // distances for this thread's two q positions
    float d[8][2];
    const float ibn0 = 1.0f / fmaxf(sqrtf(unpack_sum(bb[0])), 1e-12f);
    const float ibn1 = 1.0f / fmaxf(sqrtf(unpack_sum(bb[1])), 1e-12f);
    #pragma unroll
    for (int r = 0; r < 8; r++) {
        d[r][0] = 1.0f - unpack_sum(acc[r][0]) * s_inv[r] * ibn0;
        d[r][1] = 1.0f - unpack_sum(acc[r][1]) * s_inv[r] * ibn1;
    }

    // transpose into smem: s_d[r*512 + pos], pos = local q offset
    __syncthreads();                        // everyone done reading s_feat
    #pragma unroll
    for (int r = 0; r < 8; r++) {
        s_mem[r * 512 + tid]       = d[r][0];
        s_mem[r * 512 + tid + 256] = d[r][1];
    }
    __syncthreads();

    // warp w: top-4 of row r0+w within this chunk (value desc, index asc)
    {
        float v[16];
        #pragma unroll
        for (int t = 0; t < 16; t++)
            v[t] = s_mem[w * 512 + lane * 16 + t];

        const int out_base = ((r0 + w) * 4 + blockIdx.x) * 4;
        for (int k = 0; k < K_; k++) {
            float bv = -CUDART_INF_F; int bp = 1 << 30;
            #pragma unroll
            for (int t = 0; t < 16; t++) {
                if (v[t] > bv) { bv = v[t]; bp = lane * 16 + t; }  // asc t: > keeps low idx
            }
            #pragma unroll
            for (int o = 16; o > 0; o >>= 1) {
                float ov = __shfl_xor_sync(0xffffffffu, bv, o);
                int   op = __shfl_xor_sync(0xffffffffu, bp, o);
                if (ov > bv || (ov == bv && op < bp)) { bv = ov; bp = op; }
            }
            // mask winner locally
            if ((bp >> 4) == lane) v[bp & 15] = -CUDART_INF_F;
            if (lane == 0) {
                g_cv[out_base + k] = bv;
                g_ci[out_base + k] = qb + bp;
            }
        }
    }
}

// ---------------------------------------------------------------------------
// Kernel 3: merge 16 candidates -> global top-4 per row. 32 blocks x 8 warps,
// one warp per row. Candidates have distinct q indices; compare
// (value desc, index asc).
// ---------------------------------------------------------------------------
__global__ void merge_kernel() {
    const int tid = threadIdx.x;
    const int lane = tid & 31, w = tid >> 5;
    const int row = blockIdx.x * 8 + w;

    float v = (lane < 16) ? g_cv[row * 16 + lane] : -CUDART_INF_F;
    int   i = (lane < 16) ? g_ci[row * 16 + lane] : (1 << 30);

    int win[K_];
    for (int k = 0; k < K_; k++) {
        float bv = v; int bi = i;
        #pragma unroll
        for (int o = 16; o > 0; o >>= 1) {
            float ov = __shfl_xor_sync(0xffffffffu, bv, o);
            int   oi = __shfl_xor_sync(0xffffffffu, bi, o);
            if (ov > bv || (ov == bv && oi < bi)) { bv = ov; bi = oi; }
        }
        if (i == bi) v = -CUDART_INF_F;     // mask winner (indices unique)
        win[k] = bi;
    }
    if (lane == 0)
        *reinterpret_cast<int4*>(&g_topk[row * K_]) =
            make_int4(win[0], win[1], win[2], win[3]);
}

// ---------------------------------------------------------------------------
// Kernel 4 (fused): grid (256, 22).
//   blockIdx.y < 21 : image gather-mean chunk (1792 float4); n is the FAST
//                     grid dim so duplicate neighbor rows hit L2.
//   blockIdx.y == 21: probs mean + argmax label + grads mean for row n.
// ---------------------------------------------------------------------------
__global__ void fused_gather_kernel(const float4* __restrict__ img4,
                                    const float* __restrict__ bank,
                                    const float* __restrict__ probs,
                                    float* __restrict__ out) {
    const int n = blockIdx.x, tid = threadIdx.x;
    const int4 ii = *reinterpret_cast<const int4*>(&g_topk[n * K_]);
    const int i0 = ii.x, i1 = ii.y, i2 = ii.z, i3 = ii.w;

    if (blockIdx.y < 21) {
        const int base = blockIdx.y * 1792 + tid;
        const float4* p0 = img4 + (size_t)i0 * IMG4_;
        const float4* p1 = img4 + (size_t)i1 * IMG4_;
        const float4* p2 = img4 + (size_t)i2 * IMG4_;
        const float4* p3 = img4 + (size_t)i3 * IMG4_;
        float4* po = reinterpret_cast<float4*>(out + OFF_IMG) + (size_t)n * IMG4_;
        #pragma unroll
        for (int t = 0; t < 7; t++) {
            const int j = base + t * 256;
            float4 a = p0[j];
            float4 b = p1[j];
            float4 c = p2[j];
            float4 d = p3[j];
            float4 r;
            r.x = 0.25f * (a.x + b.x + c.x + d.x);
            r.y = 0.25f * (a.y + b.y + c.y + d.y);
            r.z = 0.25f * (a.z + b.z + c.z + d.z);
            r.w = 0.25f * (a.w + b.w + c.w + d.w);
            __stcs(po + j, r);
        }
    } else {
        // grads mean (512)
        float* outg = out + OFF_GRADS + (size_t)n * D_;
        for (int d = tid; d < D_; d += 256)
            outg[d] = 0.25f * (bank[(size_t)i0 * D_ + d] + bank[(size_t)i1 * D_ + d] +
                               bank[(size_t)i2 * D_ + d] + bank[(size_t)i3 * D_ + d]);
        // probs mean (1000) + argmax -> label
        float* outp = out + OFF_PROBS + (size_t)n * C_;
        float bv = -CUDART_INF_F; int bc = C_;
        for (int c = tid; c < C_; c += 256) {
            float p = 0.25f * (probs[(size_t)i0 * C_ + c] + probs[(size_t)i1 * C_ + c] +
                               probs[(size_t)i2 * C_ + c] + probs[(size_t)i3 * C_ + c]);
            outp[c] = p;
            if (p > bv) { bv = p; bc = c; }          // ascending c per thread
        }
        const int lane = tid & 31, w = tid >> 5;
        __shared__ float s_wv[8];
        __shared__ int   s_wi[8];
        #pragma unroll
        for (int o = 16; o > 0; o >>= 1) {
            float ov = __shfl_xor_sync(0xffffffffu, bv, o);
            int   oi = __shfl_xor_sync(0xffffffffu, bc, o);
            if (ov > bv || (ov == bv && oi < bc)) { bv = ov; bc = oi; }
        }
        if (lane == 0) { s_wv[w] = bv; s_wi[w] = bc; }
        __syncthreads();
        if (tid == 0) {
            float v2 = s_wv[0]; int ib = s_wi[0];
            #pragma unroll
            for (int p = 1; p < 8; p++)
                if (s_wv[p] > v2 || (s_wv[p] == v2 && s_wi[p] < ib)) {
                    v2 = s_wv[p]; ib = s_wi[p];
                }
            out[OFF_LABELS + n] = (float)ib;
        }
    }
}

// ---------------------------------------------------------------------------
extern "C" void kernel_launch(void* const* d_in, const int* in_sizes, int n_in,
                              void* d_out, int out_size) {
    const float* feats = (const float*)d_in[0];   // (256, 512)
    const float* bank  = (const float*)d_in[1];   // (2048, 512)
    const float* probs = (const float*)d_in[2];   // (2048, 1000)
    const float* img   = (const float*)d_in[3];   // (2048, 3, 224, 224)
    float* out = (float*)d_out;

    transpose_kernel<<<dim3(Q_ / 32, 128 / 32), 256>>>(
        reinterpret_cast<const float4*>(bank));
    dist_kernel<<<dim3(4, 32), 256>>>(
        reinterpret_cast<const float4*>(feats));
    merge_kernel<<<32, 256>>>();
    fused_gather_kernel<<<dim3(N_, 22), 256>>>(
        reinterpret_cast<const float4*>(img), bank, probs, out);
}

// round 8
// speedup vs baseline: 1.0976x; 1.0549x over previous
#include <cuda_runtime.h>
#include <math_constants.h>

#define N_    256
#define D_    512
#define Q_    2048
#define C_    1000
#define IMG_  150528   // 3*224*224
#define IMG4_ 37632    // IMG_/4 = 21 * 1792
#define K_    4

// Output layout: labels | probs | images | grads (return order, float32)
#define OFF_LABELS 0
#define OFF_PROBS  (N_)
#define OFF_IMG    (N_ + N_*C_)
#define OFF_GRADS  (N_ + N_*C_ + N_*IMG_)

// Scratch (no cudaMalloc allowed; overwritten every call => deterministic)
__device__ float4 g_bankT[128 * Q_];     // bankT[cf4][q] : 4 MB, L2-resident
__device__ float  g_cv[N_ * 32];         // per-(row,chunk) top-4 candidate values
__device__ int    g_ci[N_ * 32];         // ... and their global q indices

// packed f32x2 FMA (ptxas only emits FFMA2 via explicit PTX)
__device__ __forceinline__ void ffma2(unsigned long long& acc,
                                      unsigned long long a,
                                      unsigned long long b) {
    asm("fma.rn.f32x2 %0, %1, %2, %0;" : "+l"(acc) : "l"(a), "l"(b));
}
__device__ __forceinline__ float unpack_sum(unsigned long long v) {
    float lo = __uint_as_float((unsigned)(v & 0xffffffffull));
    float hi = __uint_as_float((unsigned)(v >> 32));
    return lo + hi;
}

// ---------------------------------------------------------------------------
// Kernel 1: transpose bank to bankT[cf4][q] so dist's bank loads are
// warp-coalesced (consecutive q per lane).
// ---------------------------------------------------------------------------
__global__ void transpose_kernel(const float4* __restrict__ bank4) {
    __shared__ float4 tile[32][33];
    const int tx = threadIdx.x & 31;
    const int ty = threadIdx.x >> 5;
    const int qt = blockIdx.x * 32;
    const int ct = blockIdx.y * 32;
    #pragma unroll
    for (int i = 0; i < 4; i++)
        tile[ty + 8 * i][tx] = bank4[(size_t)(qt + ty + 8 * i) * 128 + ct + tx];
    __syncthreads();
    #pragma unroll
    for (int i = 0; i < 4; i++)
        g_bankT[(size_t)(ct + ty + 8 * i) * Q_ + qt + tx] = tile[tx][ty + 8 * i];
}

// ---------------------------------------------------------------------------
// Kernel 2: dist + per-chunk top-4. Grid (8 q-chunks x 16 row-groups) = 128
// blocks, 256 threads. Thread tile: 16 rows x 1 q (bank L2 traffic 64 MB,
// 8 warps/block for latency hiding). After the mainloop, the 16x256 distance
// tile goes to smem (lane-contiguous, conflict-free) and each warp extracts
// the top-4 (value desc, index asc) for 2 rows within this chunk.
// No global distance matrix is ever written.
// ---------------------------------------------------------------------------
__global__ void __launch_bounds__(256) dist_kernel(const float4* __restrict__ feats4) {
    __shared__ float s_mem[16 * 512];    // 32 KB: feats tile, then 16x256 d tile
    __shared__ float s_inv[16];
    const int tid = threadIdx.x;
    const int lane = tid & 31, w = tid >> 5;
    const int r0 = blockIdx.y * 16;
    const int qb = blockIdx.x * 256;

    float4* s_feat = reinterpret_cast<float4*>(s_mem);   // 16 x 128 float4
    #pragma unroll
    for (int i = tid; i < 16 * 128; i += 256)
        s_feat[i] = feats4[(size_t)r0 * 128 + i];
    __syncthreads();

    // feature norms: warp w reduces rows 2w and 2w+1
    #pragma unroll
    for (int rr = 2 * w; rr < 2 * w + 2; rr++) {
        float ss = 0.0f;
        #pragma unroll
        for (int c = lane; c < 128; c += 32) {
            float4 v = s_feat[rr * 128 + c];
            ss += v.x * v.x + v.y * v.y + v.z * v.z + v.w * v.w;
        }
        #pragma unroll
        for (int o = 16; o > 0; o >>= 1)
            ss += __shfl_xor_sync(0xffffffffu, ss, o);
        if (lane == 0) s_inv[rr] = 1.0f / fmaxf(sqrtf(ss), 1e-12f);
    }
    __syncthreads();

    unsigned long long acc[16];
    unsigned long long bb = 0ull;
    #pragma unroll
    for (int r = 0; r < 16; r++) acc[r] = 0ull;

    const ulonglong2* bT = reinterpret_cast<const ulonglong2*>(g_bankT) + qb + tid;
    const ulonglong2* sf = reinterpret_cast<const ulonglong2*>(s_mem);

    #pragma unroll 4
    for (int c = 0; c < 128; c++) {
        ulonglong2 b = bT[(size_t)c * Q_];
        ffma2(bb, b.x, b.x);
        ffma2(bb, b.y, b.y);
        #pragma unroll
        for (int r = 0; r < 16; r++) {
            ulonglong2 f = sf[r * 128 + c];       // warp-broadcast
            ffma2(acc[r], f.x, b.x);
            ffma2(acc[r], f.y, b.y);
        }
    }

    float d[16];
    const float ibn = 1.0f / fmaxf(sqrtf(unpack_sum(bb)), 1e-12f);
    #pragma unroll
    for (int r = 0; r < 16; r++)
        d[r] = 1.0f - unpack_sum(acc[r]) * s_inv[r] * ibn;

    // store distance tile: s_d[r*256 + tid] (conflict-free)
    __syncthreads();                      // everyone done reading s_feat
    #pragma unroll
    for (int r = 0; r < 16; r++)
        s_mem[r * 256 + tid] = d[r];
    __syncthreads();

    // warp w: per-chunk top-4 of rows 2w and 2w+1 (value desc, index asc)
    #pragma unroll
    for (int rr = 2 * w; rr < 2 * w + 2; rr++) {
        float v[8];
        #pragma unroll
        for (int t = 0; t < 8; t++)
            v[t] = s_mem[rr * 256 + t * 32 + lane];   // idx = t*32+lane (asc in t)

        const int out_base = ((r0 + rr) * 8 + blockIdx.x) * 4;
        for (int k = 0; k < K_; k++) {
            float bv = -CUDART_INF_F; int bi = 1 << 30;
            #pragma unroll
            for (int t = 0; t < 8; t++) {
                if (v[t] > bv) { bv = v[t]; bi = t * 32 + lane; } // asc idx: > keeps low
            }
            #pragma unroll
            for (int o = 16; o > 0; o >>= 1) {
                float ov = __shfl_xor_sync(0xffffffffu, bv, o);
                int   oi = __shfl_xor_sync(0xffffffffu, bi, o);
                if (ov > bv || (ov == bv && oi < bi)) { bv = ov; bi = oi; }
            }
            // mask the winner locally (static indexing only)
            #pragma unroll
            for (int t = 0; t < 8; t++)
                if (bi == t * 32 + lane) v[t] = -CUDART_INF_F;
            if (lane == 0) {
                g_cv[out_base + k] = bv;
                g_ci[out_base + k] = qb + bi;
            }
        }
    }
}

// ---------------------------------------------------------------------------
// Kernel 3 (fused): grid (256, 22). Every block first re-derives the global
// top-4 for its row from the 32 per-chunk candidates (warp-0 merge, ~200cyc,
// free under a DRAM-bound kernel). Then:
//   blockIdx.y < 21 : image gather-mean chunk (1792 float4); n is the FAST
//                     grid dim so duplicate neighbor rows hit L2.
//   blockIdx.y == 21: probs mean + argmax label + grads mean for row n.
// ---------------------------------------------------------------------------
__global__ void fused_gather_kernel(const float4* __restrict__ img4,
                                    const float* __restrict__ bank,
                                    const float* __restrict__ probs,
                                    float* __restrict__ out) {
    const int n = blockIdx.x, tid = threadIdx.x;
    const int lane = tid & 31, w = tid >> 5;

    __shared__ int4 s_ii;
    if (w == 0) {
        // candidate indices are globally unique -> mask by index is safe
        float v = g_cv[n * 32 + lane];
        int   i = g_ci[n * 32 + lane];
        int win[K_];
        for (int k = 0; k < K_; k++) {
            float bv = v; int bi = i;
            #pragma unroll
            for (int o = 16; o > 0; o >>= 1) {
                float ov = __shfl_xor_sync(0xffffffffu, bv, o);
                int   oi = __shfl_xor_sync(0xffffffffu, bi, o);
                if (ov > bv || (ov == bv && oi < bi)) { bv = ov; bi = oi; }
            }
            if (i == bi) v = -CUDART_INF_F;
            win[k] = bi;
        }
        if (lane == 0) s_ii = make_int4(win[0], win[1], win[2], win[3]);
    }
    __syncthreads();
    const int i0 = s_ii.x, i1 = s_ii.y, i2 = s_ii.z, i3 = s_ii.w;

    if (blockIdx.y < 21) {
        const int base = blockIdx.y * 1792 + tid;
        const float4* p0 = img4 + (size_t)i0 * IMG4_;
        const float4* p1 = img4 + (size_t)i1 * IMG4_;
        const float4* p2 = img4 + (size_t)i2 * IMG4_;
        const float4* p3 = img4 + (size_t)i3 * IMG4_;
        float4* po = reinterpret_cast<float4*>(out + OFF_IMG) + (size_t)n * IMG4_;
        #pragma unroll
        for (int t = 0; t < 7; t++) {
            const int j = base + t * 256;
            float4 a = p0[j];
            float4 b = p1[j];
            float4 c = p2[j];
            float4 d = p3[j];
            float4 r;
            r.x = 0.25f * (a.x + b.x + c.x + d.x);
            r.y = 0.25f * (a.y + b.y + c.y + d.y);
            r.z = 0.25f * (a.z + b.z + c.z + d.z);
            r.w = 0.25f * (a.w + b.w + c.w + d.w);
            __stcs(po + j, r);
        }
    } else {
        // grads mean (512)
        float* outg = out + OFF_GRADS + (size_t)n * D_;
        for (int d = tid; d < D_; d += 256)
            outg[d] = 0.25f * (bank[(size_t)i0 * D_ + d] + bank[(size_t)i1 * D_ + d] +
                               bank[(size_t)i2 * D_ + d] + bank[(size_t)i3 * D_ + d]);
        // probs mean (1000) + argmax -> label
        float* outp = out + OFF_PROBS + (size_t)n * C_;
        float bv = -CUDART_INF_F; int bc = C_;
        for (int c = tid; c < C_; c += 256) {
            float p = 0.25f * (probs[(size_t)i0 * C_ + c] + probs[(size_t)i1 * C_ + c] +
                               probs[(size_t)i2 * C_ + c] + probs[(size_t)i3 * C_ + c]);
            outp[c] = p;
            if (p > bv) { bv = p; bc = c; }          // ascending c per thread
        }
        __shared__ float s_wv[8];
        __shared__ int   s_wi[8];
        #pragma unroll
        for (int o = 16; o > 0; o >>= 1) {
            float ov = __shfl_xor_sync(0xffffffffu, bv, o);
            int   oi = __shfl_xor_sync(0xffffffffu, bc, o);
            if (ov > bv || (ov == bv && oi < bc)) { bv = ov; bc = oi; }
        }
        if (lane == 0) { s_wv[w] = bv; s_wi[w] = bc; }
        __syncthreads();
        if (tid == 0) {
            float v2 = s_wv[0]; int ib = s_wi[0];
            #pragma unroll
            for (int p = 1; p < 8; p++)
                if (s_wv[p] > v2 || (s_wv[p] == v2 && s_wi[p] < ib)) {
                    v2 = s_wv[p]; ib = s_wi[p];
                }
            out[OFF_LABELS + n] = (float)ib;
        }
    }
}

// ---------------------------------------------------------------------------
extern "C" void kernel_launch(void* const* d_in, const int* in_sizes, int n_in,
                              void* d_out, int out_size) {
    const float* feats = (const float*)d_in[0];   // (256, 512)
    const float* bank  = (const float*)d_in[1];   // (2048, 512)
    const float* probs = (const float*)d_in[2];   // (2048, 1000)
    const float* img   = (const float*)d_in[3];   // (2048, 3, 224, 224)
    float* out = (float*)d_out;

    transpose_kernel<<<dim3(Q_ / 32, 128 / 32), 256>>>(
        reinterpret_cast<const float4*>(bank));
    dist_kernel<<<dim3(8, 16), 256>>>(
        reinterpret_cast<const float4*>(feats));
    fused_gather_kernel<<<dim3(N_, 22), 256>>>(
        reinterpret_cast<const float4*>(img), bank, probs, out);
}

// round 9
// speedup vs baseline: 1.1157x; 1.0165x over previous
#include <cuda_runtime.h>
#include <math_constants.h>

#define N_    256
#define D_    512
#define Q_    2048
#define C_    1000
#define IMG_  150528   // 3*224*224
#define IMG4_ 37632    // IMG_/4 = 21 * 1792
#define K_    4

// Output layout: labels | probs | images | grads (return order, float32)
#define OFF_LABELS 0
#define OFF_PROBS  (N_)
#define OFF_IMG    (N_ + N_*C_)
#define OFF_GRADS  (N_ + N_*C_ + N_*IMG_)

#define NQCH 16                 // q-chunks (128 q each)
#define NCAND (NQCH * K_)       // 64 candidates per row

// Scratch (no cudaMalloc allowed; overwritten every call => deterministic)
__device__ float4 g_bankT[128 * Q_];     // bankT[cf4][q] : 4 MB, L2-resident
__device__ float  g_cv[N_ * NCAND];      // per-(row,chunk) top-4 candidate values
__device__ int    g_ci[N_ * NCAND];      // ... and their global q indices

// packed f32x2 FMA (ptxas only emits FFMA2 via explicit PTX)
__device__ __forceinline__ void ffma2(unsigned long long& acc,
                                      unsigned long long a,
                                      unsigned long long b) {
    asm("fma.rn.f32x2 %0, %1, %2, %0;" : "+l"(acc) : "l"(a), "l"(b));
}
__device__ __forceinline__ float unpack_sum(unsigned long long v) {
    float lo = __uint_as_float((unsigned)(v & 0xffffffffull));
    float hi = __uint_as_float((unsigned)(v >> 32));
    return lo + hi;
}

// ---------------------------------------------------------------------------
// Kernel 1: transpose bank to bankT[cf4][q] so dist's bank loads are
// warp-coalesced (consecutive q per lane).
// ---------------------------------------------------------------------------
__global__ void transpose_kernel(const float4* __restrict__ bank4) {
    __shared__ float4 tile[32][33];
    const int tx = threadIdx.x & 31;
    const int ty = threadIdx.x >> 5;
    const int qt = blockIdx.x * 32;
    const int ct = blockIdx.y * 32;
    #pragma unroll
    for (int i = 0; i < 4; i++)
        tile[ty + 8 * i][tx] = bank4[(size_t)(qt + ty + 8 * i) * 128 + ct + tx];
    __syncthreads();
    #pragma unroll
    for (int i = 0; i < 4; i++)
        g_bankT[(size_t)(ct + ty + 8 * i) * Q_ + qt + tx] = tile[tx][ty + 8 * i];
}

// ---------------------------------------------------------------------------
// Kernel 2: dist + per-chunk top-4. Grid (16 q-chunks x 16 row-groups) = 256
// blocks, 256 threads. Thread (h, ql): h = tid>>7 selects rows 8h..8h+7,
// ql = tid&127 selects q = qb + ql. 8 accumulators/thread -> ~45 regs ->
// 2 blocks/SM co-resident (16 warps/SM) for L2-latency hiding.
// Bank L2 traffic: 16 row-groups x 4 MB = 64 MB (duplicate half-pair loads
// hit L1). Per-chunk top-4 (value desc, index asc) extracted in-block.
// No global distance matrix is ever written.
// ---------------------------------------------------------------------------
__global__ void __launch_bounds__(256) dist_kernel(const float4* __restrict__ feats4) {
    __shared__ float s_mem[16 * 512];    // 32 KB: feats tile, then 16x128 d tile
    __shared__ float s_inv[16];
    const int tid = threadIdx.x;
    const int lane = tid & 31, w = tid >> 5;
    const int h  = tid >> 7;             // row-half: 0 or 1
    const int ql = tid & 127;            // local q
    const int r0 = blockIdx.y * 16;
    const int qb = blockIdx.x * 128;

    float4* s_feat = reinterpret_cast<float4*>(s_mem);   // 16 x 128 float4
    #pragma unroll
    for (int i = tid; i < 16 * 128; i += 256)
        s_feat[i] = feats4[(size_t)r0 * 128 + i];
    __syncthreads();

    // feature norms: warp w reduces rows 2w and 2w+1
    #pragma unroll
    for (int rr = 2 * w; rr < 2 * w + 2; rr++) {
        float ss = 0.0f;
        #pragma unroll
        for (int c = lane; c < 128; c += 32) {
            float4 v = s_feat[rr * 128 + c];
            ss += v.x * v.x + v.y * v.y + v.z * v.z + v.w * v.w;
        }
        #pragma unroll
        for (int o = 16; o > 0; o >>= 1)
            ss += __shfl_xor_sync(0xffffffffu, ss, o);
        if (lane == 0) s_inv[rr] = 1.0f / fmaxf(sqrtf(ss), 1e-12f);
    }
    __syncthreads();

    unsigned long long acc[8];
    unsigned long long bb = 0ull;
    #pragma unroll
    for (int r = 0; r < 8; r++) acc[r] = 0ull;

    const ulonglong2* bT = reinterpret_cast<const ulonglong2*>(g_bankT) + qb + ql;
    const ulonglong2* sf = reinterpret_cast<const ulonglong2*>(s_mem) + (h * 8) * 128;

    #pragma unroll 4
    for (int c = 0; c < 128; c++) {
        ulonglong2 b = bT[(size_t)c * Q_];
        ffma2(bb, b.x, b.x);
        ffma2(bb, b.y, b.y);
        #pragma unroll
        for (int r = 0; r < 8; r++) {
            ulonglong2 f = sf[r * 128 + c];       // warp-broadcast
            ffma2(acc[r], f.x, b.x);
            ffma2(acc[r], f.y, b.y);
        }
    }

    float d[8];
    const float ibn = 1.0f / fmaxf(sqrtf(unpack_sum(bb)), 1e-12f);
    #pragma unroll
    for (int r = 0; r < 8; r++)
        d[r] = 1.0f - unpack_sum(acc[r]) * s_inv[h * 8 + r] * ibn;

    // store distance tile: s_d[rr * 128 + ql] (warp-contiguous, conflict-free)
    __syncthreads();                      // everyone done reading s_feat
    #pragma unroll
    for (int r = 0; r < 8; r++)
        s_mem[(h * 8 + r) * 128 + ql] = d[r];
    __syncthreads();

    // warp w: per-chunk top-4 of rows 2w and 2w+1 (value desc, index asc)
    #pragma unroll
    for (int rr = 2 * w; rr < 2 * w + 2; rr++) {
        float v[4];
        #pragma unroll
        for (int t = 0; t < 4; t++)
            v[t] = s_mem[rr * 128 + t * 32 + lane];   // local idx = t*32+lane

        const int out_base = ((r0 + rr) * NQCH + blockIdx.x) * K_;
        for (int k = 0; k < K_; k++) {
            float bv = -CUDART_INF_F; int bi = 1 << 30;
            #pragma unroll
            for (int t = 0; t < 4; t++) {
                if (v[t] > bv) { bv = v[t]; bi = t * 32 + lane; } // asc idx: > keeps low
            }
            #pragma unroll
            for (int o = 16; o > 0; o >>= 1) {
                float ov = __shfl_xor_sync(0xffffffffu, bv, o);
                int   oi = __shfl_xor_sync(0xffffffffu, bi, o);
                if (ov > bv || (ov == bv && oi < bi)) { bv = ov; bi = oi; }
            }
            // mask the winner locally (static indexing only)
            #pragma unroll
            for (int t = 0; t < 4; t++)
                if (bi == t * 32 + lane) v[t] = -CUDART_INF_F;
            if (lane == 0) {
                g_cv[out_base + k] = bv;
                g_ci[out_base + k] = qb + bi;
            }
        }
    }
}

// ---------------------------------------------------------------------------
// Kernel 3 (fused): grid (256, 22). Every block first re-derives the global
// top-4 for its row from the 64 per-chunk candidates (warp-0 merge, 2 cands
// per lane, ~250 cyc — free under a DRAM-bound kernel). Then:
//   blockIdx.y < 21 : image gather-mean chunk (1792 float4); n is the FAST
//                     grid dim so duplicate neighbor rows hit L2.
//   blockIdx.y == 21: probs mean + argmax label + grads mean for row n.
// ---------------------------------------------------------------------------
__global__ void fused_gather_kernel(const float4* __restrict__ img4,
                                    const float* __restrict__ bank,
                                    const float* __restrict__ probs,
                                    float* __restrict__ out) {
    const int n = blockIdx.x, tid = threadIdx.x;
    const int lane = tid & 31, w = tid >> 5;

    __shared__ int4 s_ii;
    if (w == 0) {
        // candidate indices are globally unique -> mask by index is safe
        float v0 = g_cv[n * NCAND + lane];
        float v1 = g_cv[n * NCAND + 32 + lane];
        int   c0 = g_ci[n * NCAND + lane];
        int   c1 = g_ci[n * NCAND + 32 + lane];
        int win[K_];
        for (int k = 0; k < K_; k++) {
            float bv; int bi;
            if (v0 > v1 || (v0 == v1 && c0 < c1)) { bv = v0; bi = c0; }
            else                                   { bv = v1; bi = c1; }
            #pragma unroll
            for (int o = 16; o > 0; o >>= 1) {
                float ov = __shfl_xor_sync(0xffffffffu, bv, o);
                int   oi = __shfl_xor_sync(0xffffffffu, bi, o);
                if (ov > bv || (ov == bv && oi < bi)) { bv = ov; bi = oi; }
            }
            if (c0 == bi) v0 = -CUDART_INF_F;
            if (c1 == bi) v1 = -CUDART_INF_F;
            win[k] = bi;
        }
        if (lane == 0) s_ii = make_int4(win[0], win[1], win[2], win[3]);
    }
    __syncthreads();
    const int i0 = s_ii.x, i1 = s_ii.y, i2 = s_ii.z, i3 = s_ii.w;

    if (blockIdx.y < 21) {
        const int base = blockIdx.y * 1792 + tid;
        const float4* p0 = img4 + (size_t)i0 * IMG4_;
        const float4* p1 = img4 + (size_t)i1 * IMG4_;
        const float4* p2 = img4 + (size_t)i2 * IMG4_;
        const float4* p3 = img4 + (size_t)i3 * IMG4_;
        float4* po = reinterpret_cast<float4*>(out + OFF_IMG) + (size_t)n * IMG4_;
        #pragma unroll
        for (int t = 0; t < 7; t++) {
            const int j = base + t * 256;
            float4 a = p0[j];
            float4 b = p1[j];
            float4 c = p2[j];
            float4 d = p3[j];
            float4 r;
            r.x = 0.25f * (a.x + b.x + c.x + d.x);
            r.y = 0.25f * (a.y + b.y + c.y + d.y);
            r.z = 0.25f * (a.z + b.z + c.z + d.z);
            r.w = 0.25f * (a.w + b.w + c.w + d.w);
            __stcs(po + j, r);
        }
    } else {
        // grads mean (512)
        float* outg = out + OFF_GRADS + (size_t)n * D_;
        for (int d = tid; d < D_; d += 256)
            outg[d] = 0.25f * (bank[(size_t)i0 * D_ + d] + bank[(size_t)i1 * D_ + d] +
                               bank[(size_t)i2 * D_ + d] + bank[(size_t)i3 * D_ + d]);
        // probs mean (1000) + argmax -> label
        float* outp = out + OFF_PROBS + (size_t)n * C_;
        float bv = -CUDART_INF_F; int bc = C_;
        for (int c = tid; c < C_; c += 256) {
            float p = 0.25f * (probs[(size_t)i0 * C_ + c] + probs[(size_t)i1 * C_ + c] +
                               probs[(size_t)i2 * C_ + c] + probs[(size_t)i3 * C_ + c]);
            outp[c] = p;
            if (p > bv) { bv = p; bc = c; }          // ascending c per thread
        }
        __shared__ float s_wv[8];
        __shared__ int   s_wi[8];
        #pragma unroll
        for (int o = 16; o > 0; o >>= 1) {
            float ov = __shfl_xor_sync(0xffffffffu, bv, o);
            int   oi = __shfl_xor_sync(0xffffffffu, bc, o);
            if (ov > bv || (ov == bv && oi < bc)) { bv = ov; bc = oi; }
        }
        if (lane == 0) { s_wv[w] = bv; s_wi[w] = bc; }
        __syncthreads();
        if (tid == 0) {
            float v2 = s_wv[0]; int ib = s_wi[0];
            #pragma unroll
            for (int p = 1; p < 8; p++)
                if (s_wv[p] > v2 || (s_wv[p] == v2 && s_wi[p] < ib)) {
                    v2 = s_wv[p]; ib = s_wi[p];
                }
            out[OFF_LABELS + n] = (float)ib;
        }
    }
}

// ---------------------------------------------------------------------------
extern "C" void kernel_launch(void* const* d_in, const int* in_sizes, int n_in,
                              void* d_out, int out_size) {
    const float* feats = (const float*)d_in[0];   // (256, 512)
    const float* bank  = (const float*)d_in[1];   // (2048, 512)
    const float* probs = (const float*)d_in[2];   // (2048, 1000)
    const float* img   = (const float*)d_in[3];   // (2048, 3, 224, 224)
    float* out = (float*)d_out;

    transpose_kernel<<<dim3(Q_ / 32, 128 / 32), 256>>>(
        reinterpret_cast<const float4*>(bank));
    dist_kernel<<<dim3(NQCH, 16), 256>>>(
        reinterpret_cast<const float4*>(feats));
    fused_gather_kernel<<<dim3(N_, 22), 256>>>(
        reinterpret_cast<const float4*>(img), bank, probs, out);
}